// round 14
// baseline (speedup 1.0000x reference)
#include <cuda_runtime.h>
#include <cuda_bf16.h>
#include <cuda_fp16.h>
#include <stdint.h>
#include <math.h>

#define N_NODES 20000
#define MPAD    20096          /* 157 * 128, /64 = 314 */
#define N_EDGES 320000
#define ETOT    (N_EDGES + N_NODES)
#define FEAT    64
#define HID     128
#define KIN     (HID + FEAT)   /* 192 */
#define NEG     0.2f

typedef __nv_bfloat16 bf16;

/* ------------------ scratch (device globals) ----------------------------- */
__device__ __align__(256) bf16  g_xinh[MPAD * KIN];
__device__ __align__(256) bf16  g_xinl[MPAD * KIN];
__device__ __align__(256) bf16  g_x0h [MPAD * HID];
__device__ __align__(256) bf16  g_x0l [MPAD * HID];
__device__ __align__(256) __half g_xl1h[MPAD * 512];     /* xl1 fp16 */
__device__ __align__(256) float  g_xr1f[MPAD * 512];     /* xr1 fp32 */
__device__ __align__(256) bf16  g_x1h [MPAD * 4 * HID];
__device__ __align__(256) bf16  g_x1l [MPAD * 4 * HID];
__device__ __align__(256) __half g_xl2h[MPAD * 128];
__device__ __align__(256) float  g_xr2f[MPAD * 128];
/* merged transposed split weights: [N,K] K-major */
__device__ __align__(256) bf16  g_pWh [HID * KIN],   g_pWl [HID * KIN];
__device__ __align__(256) bf16  g_W1h [1024 * HID],  g_W1l [1024 * HID];
__device__ __align__(256) bf16  g_W2h [256 * 4 * HID], g_W2l [256 * 4 * HID];
__device__ int   g_deg[N_NODES];    /* invariant: all-zero at launch entry */
__device__ int   g_off[N_NODES + 1];
__device__ int   g_cur[N_NODES];
__device__ int   g_srcs[ETOT];

/* ------------------ pack helpers ---------------------------------------- */
__device__ __forceinline__ unsigned int pack2(float a, float b) {
    union { __nv_bfloat162 v; unsigned int u; } c;
    c.v = __nv_bfloat162(__float2bfloat16(a), __float2bfloat16(b));
    return c.u;
}
__device__ __forceinline__ void split_store4(bf16* hp, bf16* lp, size_t o, float4 v) {
    bf16 hx = __float2bfloat16(v.x), hy = __float2bfloat16(v.y);
    bf16 hz = __float2bfloat16(v.z), hw = __float2bfloat16(v.w);
    union { __nv_bfloat162 v; unsigned int u; } a, b;
    a.v = __nv_bfloat162(hx, hy); b.v = __nv_bfloat162(hz, hw);
    *(uint2*)(hp + o) = make_uint2(a.u, b.u);
    *(uint2*)(lp + o) = make_uint2(
        pack2(v.x - __bfloat162float(hx), v.y - __bfloat162float(hy)),
        pack2(v.z - __bfloat162float(hz), v.w - __bfloat162float(hw)));
}
__device__ __forceinline__ void split_store(bf16* h, bf16* l, size_t idx, float v) {
    bf16 hb = __float2bfloat16(v);
    h[idx] = hb;
    l[idx] = __float2bfloat16(v - __bfloat162float(hb));
}
__device__ __forceinline__ float4 ldh4(const __half* p) {
    union { uint2 u; __half2 h[2]; } U;
    U.u = *(const uint2*)p;
    float2 a = __half22float2(U.h[0]), b = __half22float2(U.h[1]);
    return make_float4(a.x, a.y, b.x, b.y);
}

/* ------------------ PTX helpers (baseline sm_80+) ------------------------ */
__device__ __forceinline__ unsigned int smem_u32(const void* p) {
    unsigned int a;
    asm("{ .reg .u64 t; cvta.to.shared.u64 t, %1; cvt.u32.u64 %0, t; }" : "=r"(a) : "l"(p));
    return a;
}
#define CP16(dst, src)  asm volatile("cp.async.cg.shared.global [%0], [%1], 16;" :: "r"(dst), "l"(src) : "memory")
#define CP_COMMIT()     asm volatile("cp.async.commit_group;" ::: "memory")
#define CP_WAIT1()      asm volatile("cp.async.wait_group 1;" ::: "memory")
#define CP_WAIT0()      asm volatile("cp.async.wait_group 0;" ::: "memory")

#define LDSM4(d, addr) \
    asm volatile("ldmatrix.sync.aligned.m8n8.x4.shared.b16 {%0,%1,%2,%3}, [%4];" \
        : "=r"((d)[0]), "=r"((d)[1]), "=r"((d)[2]), "=r"((d)[3]) : "r"(addr))

#define MMA16816(c, a, b) \
    asm volatile("mma.sync.aligned.m16n8k16.row.col.f32.bf16.bf16.f32 " \
        "{%0,%1,%2,%3}, {%4,%5,%6,%7}, {%8,%9}, {%0,%1,%2,%3};" \
        : "+f"((c)[0]), "+f"((c)[1]), "+f"((c)[2]), "+f"((c)[3]) \
        : "r"((a)[0]), "r"((a)[1]), "r"((a)[2]), "r"((a)[3]), \
          "r"((b)[0]), "r"((b)[1]))

/* ------------------ CSR scan + scatter ----------------------------------- */
__global__ void k_scan() {
    __shared__ int ps[1024];
    int t = threadIdx.x;
    const int CH = (N_NODES + 1023) / 1024;
    int base = t * CH, s = 0;
    for (int i = 0; i < CH; i++) { int idx = base + i; if (idx < N_NODES) s += g_deg[idx] + 1; }
    ps[t] = s;
    __syncthreads();
    for (int off = 1; off < 1024; off <<= 1) {
        int v = (t >= off) ? ps[t - off] : 0;
        __syncthreads();
        ps[t] += v;
        __syncthreads();
    }
    int run = ps[t] - s;
    for (int i = 0; i < CH; i++) {
        int idx = base + i;
        if (idx < N_NODES) {
            int d = g_deg[idx];
            g_deg[idx] = 0;                   /* restore invariant for next call */
            g_off[idx] = run;
            g_srcs[run] = idx;                /* self loop first */
            g_cur[idx] = run + 1;
            run += d + 1;
        }
    }
    if (t == 1023) g_off[N_NODES] = ps[1023];
}
__global__ void k_scatter(const int* __restrict__ ei) {
    int e = blockIdx.x * blockDim.x + threadIdx.x;
    if (e < N_EDGES) {
        int d = ei[N_EDGES + e];
        int p = atomicAdd(&g_cur[d], 1);
        g_srcs[p] = ei[e];
    }
}

/* ------------------ merged prep: edge count + gather + weight conv ------- */
#define PREP_C   N_EDGES
#define PREP_G   (N_NODES * KIN / 4)
#define PREP_PW  (KIN * HID)
#define PREP_W1  (HID * 512)
#define PREP_W2  (512 * HID)
#define PREP_TOT (PREP_C + PREP_G + PREP_PW + 2 * PREP_W1 + 2 * PREP_W2)

__device__ __forceinline__ void conv_one(const float* __restrict__ W,
                                         bf16* h, bf16* l, int K, int N, int idx) {
    int k = idx / N, n = idx - k * N;
    split_store(h, l, (size_t)n * K + k, W[(size_t)k * N + n]);
}

__global__ void k_prep(const int* __restrict__ ei,
                       const float* __restrict__ xp, const float* __restrict__ emb,
                       const float* __restrict__ proj_W,
                       const float* __restrict__ W1l, const float* __restrict__ W1r,
                       const float* __restrict__ W2l, const float* __restrict__ W2r)
{
    int idx = blockIdx.x * blockDim.x + threadIdx.x;
    if (idx < PREP_C) {
        atomicAdd(&g_deg[ei[N_EDGES + idx]], 1);
        return;
    }
    idx -= PREP_C;
    if (idx < PREP_G) {
        int i = idx / (KIN / 4), q = idx - i * (KIN / 4);
        int k = q * 4;
        float4 v;
        if (k < HID) {
            int id = (int)xp[i * (FEAT + 1)];
            v = *(const float4*)(emb + (size_t)id * HID + k);
        } else {
            const float* f = xp + i * (FEAT + 1) + 1 + (k - HID);
            v = make_float4(f[0], f[1], f[2], f[3]);
        }
        split_store4(g_xinh, g_xinl, (size_t)i * KIN + k, v);
        return;
    }
    idx -= PREP_G;
    if (idx < PREP_PW) { conv_one(proj_W, g_pWh, g_pWl, KIN, HID, idx); return; }
    idx -= PREP_PW;
    if (idx < PREP_W1) { conv_one(W1l, g_W1h, g_W1l, HID, 512, idx); return; }
    idx -= PREP_W1;
    if (idx < PREP_W1) { conv_one(W1r, g_W1h + 512 * HID, g_W1l + 512 * HID, HID, 512, idx); return; }
    idx -= PREP_W1;
    if (idx < PREP_W2) { conv_one(W2l, g_W2h, g_W2l, 512, HID, idx); return; }
    idx -= PREP_W2;
    if (idx < PREP_W2) { conv_one(W2r, g_W2h + 128 * 512, g_W2l + 128 * 512, 512, HID, idx); return; }
}

/* ------------------ HMMA split-bf16 GEMM --------------------------------- */
/* CTA 64x128, BK=64, 8 warps (2M x 4N), warp tile 32x32, occ 2.             */
#define PADK    72
#define A_EL    (64 * PADK)
#define B_EL    (128 * PADK)
#define OFF_AH  0
#define OFF_AL  (A_EL * 2)
#define OFF_BH  (2 * A_EL * 2)
#define OFF_BL  (2 * A_EL * 2 + B_EL * 2)
#define STG_B   ((2 * A_EL + 2 * B_EL) * 2)   /* 55296 bytes */
#define SM_SZ   (2 * STG_B)                   /* 110592 bytes */

__device__ __forceinline__ void stage_load(
    unsigned sbase, int s,
    const bf16* __restrict__ Ah, const bf16* __restrict__ Al,
    const bf16* __restrict__ Bh, const bf16* __restrict__ Bl,
    int row0, int col0, int k0, int Ktot, int tid)
{
    unsigned stb = sbase + (unsigned)(s * STG_B);
#pragma unroll
    for (int q = 0; q < 2; q++) {
        int idx = tid + 256 * q;
        int r = idx >> 3, cc = idx & 7;
        unsigned so = (unsigned)((r * PADK + cc * 8) * 2);
        size_t ga = (size_t)(row0 + r) * Ktot + k0 + cc * 8;
        CP16(stb + OFF_AH + so, Ah + ga);
        CP16(stb + OFF_AL + so, Al + ga);
    }
#pragma unroll
    for (int q = 0; q < 4; q++) {
        int idx = tid + 256 * q;
        int r = idx >> 3, cc = idx & 7;
        unsigned so = (unsigned)((r * PADK + cc * 8) * 2);
        size_t gb = (size_t)(col0 + r) * Ktot + k0 + cc * 8;
        CP16(stb + OFF_BH + so, Bh + gb);
        CP16(stb + OFF_BL + so, Bl + gb);
    }
}

/* epilogue:
 *  - Ch/Cl set         -> split-bf16 output, row stride Nld
 *  - else Hx/Fx set    -> cols [0,Nsplit) as fp16, cols [Nsplit,2N) as fp32
 */
__device__ __forceinline__ void emit2(int r, int col, float2 v,
                                      const float* __restrict__ bias, int relu,
                                      bf16* __restrict__ Ch, bf16* __restrict__ Cl,
                                      __half* __restrict__ Hx, float* __restrict__ Fx,
                                      int Nsplit, int Nld)
{
    if (bias) { v.x += bias[col]; v.y += bias[col + 1]; }
    if (relu) { v.x = fmaxf(v.x, 0.f); v.y = fmaxf(v.y, 0.f); }
    if (Ch) {
        size_t o = (size_t)r * Nld + col;
        bf16 hx = __float2bfloat16(v.x), hy = __float2bfloat16(v.y);
        union { __nv_bfloat162 b; unsigned u; } H;
        H.b = __nv_bfloat162(hx, hy);
        *(unsigned*)(Ch + o) = H.u;
        *(unsigned*)(Cl + o) = pack2(v.x - __bfloat162float(hx),
                                     v.y - __bfloat162float(hy));
    } else if (col < Nsplit) {
        *(__half2*)(Hx + (size_t)r * Nsplit + col) = __floats2half2_rn(v.x, v.y);
    } else {
        *(float2*)(Fx + (size_t)r * Nsplit + (col - Nsplit)) = v;
    }
}

__global__ __launch_bounds__(256, 2)
void mm_bf16(const bf16* __restrict__ Ah, const bf16* __restrict__ Al,
             const bf16* __restrict__ Bh, const bf16* __restrict__ Bl,
             const float* __restrict__ bias,
             bf16* __restrict__ Ch, bf16* __restrict__ Cl,
             __half* __restrict__ Hx, float* __restrict__ Fx,
             int Ktot, int Nsplit, int Nld, int relu)
{
    extern __shared__ char smem[];
    unsigned sbase = smem_u32(smem);
    int tid = threadIdx.x;
    int lane = tid & 31, wrp = tid >> 5;
    int wm = wrp & 1, wn = wrp >> 1;
    int row0 = blockIdx.y * 64, col0 = blockIdx.x * 128;

    float c[2][4][4];
#pragma unroll
    for (int i = 0; i < 2; i++)
#pragma unroll
        for (int j = 0; j < 4; j++)
#pragma unroll
            for (int q = 0; q < 4; q++) c[i][j][q] = 0.f;

    int nk = Ktot >> 6;
    stage_load(sbase, 0, Ah, Al, Bh, Bl, row0, col0, 0, Ktot, tid);
    CP_COMMIT();

    for (int it = 0; it < nk; it++) {
        if (it + 1 < nk) {
            stage_load(sbase, (it + 1) & 1, Ah, Al, Bh, Bl, row0, col0,
                       (it + 1) << 6, Ktot, tid);
            CP_COMMIT();
            CP_WAIT1();
        } else {
            CP_WAIT0();
        }
        __syncthreads();

        unsigned stb = sbase + (unsigned)((it & 1) * STG_B);

#pragma unroll
        for (int ks = 0; ks < 4; ks++) {
            int kc = ks * 16;
            unsigned ah[2][4], al[2][4], bh[2][4], bl[2][4];
#pragma unroll
            for (int ma = 0; ma < 2; ma++) {
                int el = (wm * 32 + ma * 16 + (lane & 15)) * PADK
                       + kc + ((lane >> 4) << 3);
                LDSM4(ah[ma], stb + OFF_AH + el * 2);
                LDSM4(al[ma], stb + OFF_AL + el * 2);
            }
#pragma unroll
            for (int nb = 0; nb < 2; nb++) {
                int n = wn * 32 + nb * 16 + ((lane >> 4) << 3) + (lane & 7);
                int el = n * PADK + kc + (((lane >> 3) & 1) << 3);
                LDSM4(bh[nb], stb + OFF_BH + el * 2);
                LDSM4(bl[nb], stb + OFF_BL + el * 2);
            }
#pragma unroll
            for (int ma = 0; ma < 2; ma++)
#pragma unroll
                for (int na = 0; na < 4; na++) {
                    const unsigned* bph = &bh[na >> 1][(na & 1) * 2];
                    const unsigned* bpl = &bl[na >> 1][(na & 1) * 2];
                    MMA16816(c[ma][na], ah[ma], bph);
                    MMA16816(c[ma][na], ah[ma], bpl);
                    MMA16816(c[ma][na], al[ma], bph);
                }
        }
        __syncthreads();
    }

#pragma unroll
    for (int ma = 0; ma < 2; ma++) {
        int r0 = row0 + wm * 32 + ma * 16 + (lane >> 2);
#pragma unroll
        for (int na = 0; na < 4; na++) {
            int col = col0 + wn * 32 + na * 8 + ((lane & 3) << 1);
            emit2(r0,     col, make_float2(c[ma][na][0], c[ma][na][1]),
                  bias, relu, Ch, Cl, Hx, Fx, Nsplit, Nld);
            emit2(r0 + 8, col, make_float2(c[ma][na][2], c[ma][na][3]),
                  bias, relu, Ch, Cl, Hx, Fx, Nsplit, Nld);
        }
    }
}

/* ------------------ GATv2 aggregation helpers ---------------------------- */
__device__ __forceinline__ float lrelu(float x) { return x > 0.f ? x : NEG * x; }

struct OSM { float m, s; float4 acc; };
__device__ __forceinline__ void osm_init(OSM& o) {
    o.m = -1e30f; o.s = 0.f; o.acc = make_float4(0.f, 0.f, 0.f, 0.f);
}
__device__ __forceinline__ void osm_step(OSM& o, float4 l4, float4 r4, float4 a4) {
    float p = lrelu(l4.x + r4.x) * a4.x;
    p      += lrelu(l4.y + r4.y) * a4.y;
    p      += lrelu(l4.z + r4.z) * a4.z;
    p      += lrelu(l4.w + r4.w) * a4.w;
#pragma unroll
    for (int off = 16; off > 0; off >>= 1) p += __shfl_xor_sync(0xffffffffu, p, off);
    float mn = fmaxf(o.m, p);
    float cc = __expf(o.m - mn);
    float wg = __expf(p - mn);
    o.s = o.s * cc + wg;
    o.acc.x = o.acc.x * cc + wg * l4.x;
    o.acc.y = o.acc.y * cc + wg * l4.y;
    o.acc.z = o.acc.z * cc + wg * l4.z;
    o.acc.w = o.acc.w * cc + wg * l4.w;
    o.m = mn;
}
__device__ __forceinline__ void osm_merge(OSM& a, const OSM& b) {
    float mn = fmaxf(a.m, b.m);
    float ca = __expf(a.m - mn), cb = __expf(b.m - mn);
    a.s = a.s * ca + b.s * cb;
    a.acc.x = a.acc.x * ca + b.acc.x * cb;
    a.acc.y = a.acc.y * ca + b.acc.y * cb;
    a.acc.z = a.acc.z * ca + b.acc.z * cb;
    a.acc.w = a.acc.w * ca + b.acc.w * cb;
    a.m = mn;
}

/* ILP-4 edge loop shared by both agg kernels. D = feature row stride. */
template <int D>
__device__ __forceinline__ OSM agg_loop(const __half* __restrict__ xl, int cb,
                                        float4 r4, float4 a4, int j, int end)
{
    OSM o0, o1, o2, o3;
    osm_init(o0); osm_init(o1); osm_init(o2); osm_init(o3);
    int rem = (end - j) & 3;
    while (rem--) {
        float4 l4 = ldh4(xl + (size_t)g_srcs[j] * D + cb);
        osm_step(o0, l4, r4, a4);
        j++;
    }
    for (; j < end; j += 4) {
        int sA = g_srcs[j], sB = g_srcs[j + 1], sC = g_srcs[j + 2], sD = g_srcs[j + 3];
        float4 lA = ldh4(xl + (size_t)sA * D + cb);
        float4 lB = ldh4(xl + (size_t)sB * D + cb);
        float4 lC = ldh4(xl + (size_t)sC * D + cb);
        float4 lD = ldh4(xl + (size_t)sD * D + cb);
        osm_step(o0, lA, r4, a4);
        osm_step(o1, lB, r4, a4);
        osm_step(o2, lC, r4, a4);
        osm_step(o3, lD, r4, a4);
    }
    osm_merge(o0, o1);
    osm_merge(o2, o3);
    osm_merge(o0, o2);
    return o0;
}

/* ------------------ layer-1 aggregation (fp16 xl) ------------------------ */
__global__ void gat_agg1(const __half* __restrict__ xl, const float* __restrict__ xr,
                         const float* __restrict__ att, const float* __restrict__ bias,
                         bf16* __restrict__ oh, bf16* __restrict__ ol)
{
    const int HEADS = 4, D = 512;
    int w = (blockIdx.x * blockDim.x + threadIdx.x) >> 5;
    int lane = threadIdx.x & 31;
    if (w >= N_NODES * HEADS) return;
    int dst = w / HEADS;
    int h   = w - dst * HEADS;
    int cb = h * HID + lane * 4;

    float4 a4 = *(const float4*)(att + h * HID + lane * 4);
    float4 r4 = *(const float4*)(xr + (size_t)dst * D + cb);

    OSM o = agg_loop<D>(xl, cb, r4, a4, g_off[dst], g_off[dst + 1]);

    float inv = 1.f / (o.s + 1e-16f);
    float4 bb = *(const float4*)(bias + h * HID + lane * 4);
    float4 o4;
    o4.x = fmaxf(o.acc.x * inv + bb.x, 0.f);
    o4.y = fmaxf(o.acc.y * inv + bb.y, 0.f);
    o4.z = fmaxf(o.acc.z * inv + bb.z, 0.f);
    o4.w = fmaxf(o.acc.w * inv + bb.w, 0.f);
    split_store4(oh, ol, (size_t)dst * 512 + cb, o4);
}

/* -------- layer-2 aggregation (fp16 xl) fused with output projection ---- */
__global__ void gat_out(const __half* __restrict__ xl, const float* __restrict__ xr,
                        const float* __restrict__ att, const float* __restrict__ bias,
                        const float* __restrict__ W, const float* __restrict__ ob,
                        float* __restrict__ y)
{
    const int D = 128;
    __shared__ float Ws[HID * 10];
    __shared__ float bs[10];
    for (int i = threadIdx.x; i < HID * 10; i += blockDim.x) Ws[i] = W[i];
    if (threadIdx.x < 10) bs[threadIdx.x] = ob[threadIdx.x];
    __syncthreads();

    int w = (blockIdx.x * blockDim.x + threadIdx.x) >> 5;
    int lane = threadIdx.x & 31;
    if (w >= N_NODES) return;
    int dst = w;
    int cb = lane * 4;

    float4 a4 = *(const float4*)(att + cb);
    float4 r4 = *(const float4*)(xr + (size_t)dst * D + cb);

    OSM o = agg_loop<D>(xl, cb, r4, a4, g_off[dst], g_off[dst + 1]);

    float inv = 1.f / (o.s + 1e-16f);
    float4 bb = *(const float4*)(bias + cb);
    float4 o4;
    o4.x = o.acc.x * inv + bb.x;
    o4.y = o.acc.y * inv + bb.y;
    o4.z = o.acc.z * inv + bb.z;
    o4.w = o.acc.w * inv + bb.w;

    int k = lane * 4;
    float p[10];
#pragma unroll
    for (int o2 = 0; o2 < 10; o2++)
        p[o2] = o4.x * Ws[(k + 0) * 10 + o2] + o4.y * Ws[(k + 1) * 10 + o2] +
                o4.z * Ws[(k + 2) * 10 + o2] + o4.w * Ws[(k + 3) * 10 + o2];
#pragma unroll
    for (int o2 = 0; o2 < 10; o2++)
#pragma unroll
        for (int off = 16; off > 0; off >>= 1)
            p[o2] += __shfl_xor_sync(0xffffffffu, p[o2], off);
    if (lane < 10) y[(size_t)dst * 10 + lane] = p[lane] + bs[lane];
}

/* ------------------ launch ---------------------------------------------- */
extern "C" void kernel_launch(void* const* d_in, const int* in_sizes, int n_in,
                              void* d_out, int out_size)
{
    const float* x_player   = (const float*)d_in[0];
    const int*   edge_index = (const int*)  d_in[1];
    const float* emb        = (const float*)d_in[2];
    const float* proj_W     = (const float*)d_in[3];
    const float* proj_b     = (const float*)d_in[4];
    const float* W1l        = (const float*)d_in[5];
    const float* W1r        = (const float*)d_in[6];
    const float* att1       = (const float*)d_in[7];
    const float* b1         = (const float*)d_in[8];
    const float* W2l        = (const float*)d_in[9];
    const float* W2r        = (const float*)d_in[10];
    const float* att2       = (const float*)d_in[11];
    const float* b2         = (const float*)d_in[12];
    const float* out_W      = (const float*)d_in[13];
    const float* out_b      = (const float*)d_in[14];
    float* y = (float*)d_out;

    bf16 *xinh, *xinl, *x0h, *x0l, *x1h, *x1l;
    bf16 *pWh, *pWl, *W1h, *W1lo, *W2h, *W2lo;
    __half *xl1h, *xl2h;
    float *xr1f, *xr2f;
    cudaGetSymbolAddress((void**)&xinh, g_xinh); cudaGetSymbolAddress((void**)&xinl, g_xinl);
    cudaGetSymbolAddress((void**)&x0h,  g_x0h);  cudaGetSymbolAddress((void**)&x0l,  g_x0l);
    cudaGetSymbolAddress((void**)&x1h,  g_x1h);  cudaGetSymbolAddress((void**)&x1l,  g_x1l);
    cudaGetSymbolAddress((void**)&xl1h, g_xl1h); cudaGetSymbolAddress((void**)&xr1f, g_xr1f);
    cudaGetSymbolAddress((void**)&xl2h, g_xl2h); cudaGetSymbolAddress((void**)&xr2f, g_xr2f);
    cudaGetSymbolAddress((void**)&pWh,  g_pWh);  cudaGetSymbolAddress((void**)&pWl,  g_pWl);
    cudaGetSymbolAddress((void**)&W1h,  g_W1h);  cudaGetSymbolAddress((void**)&W1lo, g_W1l);
    cudaGetSymbolAddress((void**)&W2h,  g_W2h);  cudaGetSymbolAddress((void**)&W2lo, g_W2l);

    cudaFuncSetAttribute(mm_bf16, cudaFuncAttributeMaxDynamicSharedMemorySize, SM_SZ);

    /* prep (edge count + gather + weight conversion), then CSR scan+scatter */
    k_prep<<<(PREP_TOT + 255) / 256, 256>>>(edge_index, x_player, emb, proj_W,
                                            W1l, W1r, W2l, W2r);
    k_scan   <<<1, 1024>>>();
    k_scatter<<<(N_EDGES + 255) / 256, 256>>>(edge_index);

    /* proj: [MPAD,192]@[192,128] + b, relu, split-bf16 output */
    mm_bf16<<<dim3(1, MPAD / 64), 256, SM_SZ>>>(
        xinh, xinl, pWh, pWl, proj_b, x0h, x0l, nullptr, nullptr, KIN, 0, HID, 1);

    /* GAT layer 1 linear: merged GEMM N=1024 -> xl fp16 | xr fp32 */
    mm_bf16<<<dim3(8, MPAD / 64), 256, SM_SZ>>>(
        x0h, x0l, W1h, W1lo, nullptr, nullptr, nullptr, xl1h, xr1f, HID, 512, 1024, 0);
    gat_agg1<<<(N_NODES * 4 * 32 + 255) / 256, 256>>>(xl1h, xr1f, att1, b1, x1h, x1l);

    /* GAT layer 2 linear: merged GEMM N=256 -> xl fp16 | xr fp32 */
    mm_bf16<<<dim3(2, MPAD / 64), 256, SM_SZ>>>(
        x1h, x1l, W2h, W2lo, nullptr, nullptr, nullptr, xl2h, xr2f, 512, 128, 256, 0);

    /* layer-2 aggregation fused with output projection */
    gat_out<<<(N_NODES * 32 + 255) / 256, 256>>>(xl2h, xr2f, att2, b2, out_W, out_b, y);
}

// round 16
// speedup vs baseline: 1.2746x; 1.2746x over previous
#include <cuda_runtime.h>
#include <cuda_fp16.h>
#include <stdint.h>
#include <math.h>

#define N_NODES 20000
#define MPAD    20096          /* 157 * 128, /64 = 314 */
#define N_EDGES 320000
#define ETOT    (N_EDGES + N_NODES)
#define FEAT    64
#define HID     128
#define KIN     (HID + FEAT)   /* 192 */
#define NEG     0.2f

/* ------------------ scratch (device globals) ----------------------------- */
__device__ __align__(256) __half g_xin [MPAD * KIN];
__device__ __align__(256) __half g_x0  [MPAD * HID];
__device__ __align__(256) __half g_xl1h[MPAD * 512];     /* xl1 fp16 */
__device__ __align__(256) float  g_xr1f[MPAD * 512];     /* xr1 fp32 */
__device__ __align__(256) __half g_x1  [MPAD * 512];
__device__ __align__(256) __half g_xl2h[MPAD * 128];
__device__ __align__(256) float  g_xr2f[MPAD * 128];
/* transposed fp16 weights: [N,K] K-major */
__device__ __align__(256) __half g_pW [HID * KIN];
__device__ __align__(256) __half g_W1 [1024 * HID];
__device__ __align__(256) __half g_W2 [256 * 4 * HID];
__device__ int   g_deg[N_NODES];    /* invariant: all-zero at launch entry */
__device__ int   g_off[N_NODES + 1];
__device__ int   g_cur[N_NODES];
__device__ int   g_srcs[ETOT];

/* ------------------ helpers --------------------------------------------- */
__device__ __forceinline__ float4 ldh4(const __half* p) {
    union { uint2 u; __half2 h[2]; } U;
    U.u = *(const uint2*)p;
    float2 a = __half22float2(U.h[0]), b = __half22float2(U.h[1]);
    return make_float4(a.x, a.y, b.x, b.y);
}
__device__ __forceinline__ void st_h4(__half* p, float4 v) {
    union { uint2 u; __half2 h[2]; } U;
    U.h[0] = __floats2half2_rn(v.x, v.y);
    U.h[1] = __floats2half2_rn(v.z, v.w);
    *(uint2*)p = U.u;
}
__device__ __forceinline__ unsigned int smem_u32(const void* p) {
    unsigned int a;
    asm("{ .reg .u64 t; cvta.to.shared.u64 t, %1; cvt.u32.u64 %0, t; }" : "=r"(a) : "l"(p));
    return a;
}
#define CP16(dst, src)  asm volatile("cp.async.cg.shared.global [%0], [%1], 16;" :: "r"(dst), "l"(src) : "memory")
#define CP_COMMIT()     asm volatile("cp.async.commit_group;" ::: "memory")
#define CP_WAIT1()      asm volatile("cp.async.wait_group 1;" ::: "memory")
#define CP_WAIT0()      asm volatile("cp.async.wait_group 0;" ::: "memory")

#define LDSM4(d, addr) \
    asm volatile("ldmatrix.sync.aligned.m8n8.x4.shared.b16 {%0,%1,%2,%3}, [%4];" \
        : "=r"((d)[0]), "=r"((d)[1]), "=r"((d)[2]), "=r"((d)[3]) : "r"(addr))

#define MMAF16(c, a, b) \
    asm volatile("mma.sync.aligned.m16n8k16.row.col.f32.f16.f16.f32 " \
        "{%0,%1,%2,%3}, {%4,%5,%6,%7}, {%8,%9}, {%0,%1,%2,%3};" \
        : "+f"((c)[0]), "+f"((c)[1]), "+f"((c)[2]), "+f"((c)[3]) \
        : "r"((a)[0]), "r"((a)[1]), "r"((a)[2]), "r"((a)[3]), \
          "r"((b)[0]), "r"((b)[1]))

/* ------------------ CSR scan + scatter ----------------------------------- */
__global__ void k_scan() {
    __shared__ int ps[1024];
    int t = threadIdx.x;
    const int CH = (N_NODES + 1023) / 1024;
    int base = t * CH, s = 0;
    for (int i = 0; i < CH; i++) { int idx = base + i; if (idx < N_NODES) s += g_deg[idx] + 1; }
    ps[t] = s;
    __syncthreads();
    for (int off = 1; off < 1024; off <<= 1) {
        int v = (t >= off) ? ps[t - off] : 0;
        __syncthreads();
        ps[t] += v;
        __syncthreads();
    }
    int run = ps[t] - s;
    for (int i = 0; i < CH; i++) {
        int idx = base + i;
        if (idx < N_NODES) {
            int d = g_deg[idx];
            g_deg[idx] = 0;                   /* restore invariant for next call */
            g_off[idx] = run;
            g_srcs[run] = idx;                /* self loop first */
            g_cur[idx] = run + 1;
            run += d + 1;
        }
    }
    if (t == 1023) g_off[N_NODES] = ps[1023];
}
__global__ void k_scatter(const int* __restrict__ ei) {
    int e = blockIdx.x * blockDim.x + threadIdx.x;
    if (e < N_EDGES) {
        int d = ei[N_EDGES + e];
        int p = atomicAdd(&g_cur[d], 1);
        g_srcs[p] = ei[e];
    }
}

/* ------------------ merged prep: edge count + gather + weight conv ------- */
#define PREP_C   N_EDGES
#define PREP_G   (N_NODES * KIN / 4)
#define PREP_PW  (KIN * HID)
#define PREP_W1  (HID * 512)
#define PREP_W2  (512 * HID)
#define PREP_TOT (PREP_C + PREP_G + PREP_PW + 2 * PREP_W1 + 2 * PREP_W2)

__device__ __forceinline__ void conv_one(const float* __restrict__ W,
                                         __half* h, int K, int N, int idx) {
    int k = idx / N, n = idx - k * N;
    h[(size_t)n * K + k] = __float2half(W[(size_t)k * N + n]);
}

__global__ void k_prep(const int* __restrict__ ei,
                       const float* __restrict__ xp, const float* __restrict__ emb,
                       const float* __restrict__ proj_W,
                       const float* __restrict__ W1l, const float* __restrict__ W1r,
                       const float* __restrict__ W2l, const float* __restrict__ W2r)
{
    int idx = blockIdx.x * blockDim.x + threadIdx.x;
    if (idx < PREP_C) {
        atomicAdd(&g_deg[ei[N_EDGES + idx]], 1);
        return;
    }
    idx -= PREP_C;
    if (idx < PREP_G) {
        int i = idx / (KIN / 4), q = idx - i * (KIN / 4);
        int k = q * 4;
        float4 v;
        if (k < HID) {
            int id = (int)xp[i * (FEAT + 1)];
            v = *(const float4*)(emb + (size_t)id * HID + k);
        } else {
            const float* f = xp + i * (FEAT + 1) + 1 + (k - HID);
            v = make_float4(f[0], f[1], f[2], f[3]);
        }
        st_h4(g_xin + (size_t)i * KIN + k, v);
        return;
    }
    idx -= PREP_G;
    if (idx < PREP_PW) { conv_one(proj_W, g_pW, KIN, HID, idx); return; }
    idx -= PREP_PW;
    if (idx < PREP_W1) { conv_one(W1l, g_W1, HID, 512, idx); return; }
    idx -= PREP_W1;
    if (idx < PREP_W1) { conv_one(W1r, g_W1 + 512 * HID, HID, 512, idx); return; }
    idx -= PREP_W1;
    if (idx < PREP_W2) { conv_one(W2l, g_W2, 512, HID, idx); return; }
    idx -= PREP_W2;
    if (idx < PREP_W2) { conv_one(W2r, g_W2 + 128 * 512, 512, HID, idx); return; }
}

/* ------------------ HMMA fp16 GEMM --------------------------------------- */
/* C[M=MPAD, Ntot] = A[M,Ktot] @ B^T (B stored [Ntot,Ktot] K-major)          */
/* CTA 64x128, BK=64, 8 warps (2M x 4N), warp tile 32x32, occ 2.             */
#define PADK    72
#define A_EL    (64 * PADK)
#define B_EL    (128 * PADK)
#define OFF_A   0
#define OFF_B   (A_EL * 2)
#define STG_B   ((A_EL + B_EL) * 2)           /* 27648 bytes */
#define SM_SZ   (2 * STG_B)                   /* 55296 bytes */

__device__ __forceinline__ void stage_load(
    unsigned sbase, int s,
    const __half* __restrict__ A, const __half* __restrict__ B,
    int row0, int col0, int k0, int Ktot, int tid)
{
    unsigned stb = sbase + (unsigned)(s * STG_B);
#pragma unroll
    for (int q = 0; q < 2; q++) {
        int idx = tid + 256 * q;
        int r = idx >> 3, cc = idx & 7;
        unsigned so = (unsigned)((r * PADK + cc * 8) * 2);
        CP16(stb + OFF_A + so, A + (size_t)(row0 + r) * Ktot + k0 + cc * 8);
    }
#pragma unroll
    for (int q = 0; q < 4; q++) {
        int idx = tid + 256 * q;
        int r = idx >> 3, cc = idx & 7;
        unsigned so = (unsigned)((r * PADK + cc * 8) * 2);
        CP16(stb + OFF_B + so, B + (size_t)(col0 + r) * Ktot + k0 + cc * 8);
    }
}

/* epilogue:
 *  - Ho set      -> fp16 output (bias/relu applied), row stride Nld
 *  - else Hx/Fx  -> cols [0,Nsplit) fp16 to Hx, cols [Nsplit,2N) fp32 to Fx
 */
__device__ __forceinline__ void emit2(int r, int col, float2 v,
                                      const float* __restrict__ bias, int relu,
                                      __half* __restrict__ Ho,
                                      __half* __restrict__ Hx, float* __restrict__ Fx,
                                      int Nsplit, int Nld)
{
    if (bias) { v.x += bias[col]; v.y += bias[col + 1]; }
    if (relu) { v.x = fmaxf(v.x, 0.f); v.y = fmaxf(v.y, 0.f); }
    if (Ho) {
        *(__half2*)(Ho + (size_t)r * Nld + col) = __floats2half2_rn(v.x, v.y);
    } else if (col < Nsplit) {
        *(__half2*)(Hx + (size_t)r * Nsplit + col) = __floats2half2_rn(v.x, v.y);
    } else {
        *(float2*)(Fx + (size_t)r * Nsplit + (col - Nsplit)) = v;
    }
}

__global__ __launch_bounds__(256, 2)
void mm_fp16(const __half* __restrict__ A, const __half* __restrict__ B,
             const float* __restrict__ bias,
             __half* __restrict__ Ho,
             __half* __restrict__ Hx, float* __restrict__ Fx,
             int Ktot, int Nsplit, int Nld, int relu)
{
    extern __shared__ char smem[];
    unsigned sbase = smem_u32(smem);
    int tid = threadIdx.x;
    int lane = tid & 31, wrp = tid >> 5;
    int wm = wrp & 1, wn = wrp >> 1;
    int row0 = blockIdx.y * 64, col0 = blockIdx.x * 128;

    float c[2][4][4];
#pragma unroll
    for (int i = 0; i < 2; i++)
#pragma unroll
        for (int j = 0; j < 4; j++)
#pragma unroll
            for (int q = 0; q < 4; q++) c[i][j][q] = 0.f;

    int nk = Ktot >> 6;
    stage_load(sbase, 0, A, B, row0, col0, 0, Ktot, tid);
    CP_COMMIT();

    for (int it = 0; it < nk; it++) {
        if (it + 1 < nk) {
            stage_load(sbase, (it + 1) & 1, A, B, row0, col0,
                       (it + 1) << 6, Ktot, tid);
            CP_COMMIT();
            CP_WAIT1();
        } else {
            CP_WAIT0();
        }
        __syncthreads();

        unsigned stb = sbase + (unsigned)((it & 1) * STG_B);

#pragma unroll
        for (int ks = 0; ks < 4; ks++) {
            int kc = ks * 16;
            unsigned a[2][4], b[2][4];
#pragma unroll
            for (int ma = 0; ma < 2; ma++) {
                int el = (wm * 32 + ma * 16 + (lane & 15)) * PADK
                       + kc + ((lane >> 4) << 3);
                LDSM4(a[ma], stb + OFF_A + el * 2);
            }
#pragma unroll
            for (int nb = 0; nb < 2; nb++) {
                int n = wn * 32 + nb * 16 + ((lane >> 4) << 3) + (lane & 7);
                int el = n * PADK + kc + (((lane >> 3) & 1) << 3);
                LDSM4(b[nb], stb + OFF_B + el * 2);
            }
#pragma unroll
            for (int ma = 0; ma < 2; ma++)
#pragma unroll
                for (int na = 0; na < 4; na++)
                    MMAF16(c[ma][na], a[ma], &b[na >> 1][(na & 1) * 2]);
        }
        __syncthreads();
    }

#pragma unroll
    for (int ma = 0; ma < 2; ma++) {
        int r0 = row0 + wm * 32 + ma * 16 + (lane >> 2);
#pragma unroll
        for (int na = 0; na < 4; na++) {
            int col = col0 + wn * 32 + na * 8 + ((lane & 3) << 1);
            emit2(r0,     col, make_float2(c[ma][na][0], c[ma][na][1]),
                  bias, relu, Ho, Hx, Fx, Nsplit, Nld);
            emit2(r0 + 8, col, make_float2(c[ma][na][2], c[ma][na][3]),
                  bias, relu, Ho, Hx, Fx, Nsplit, Nld);
        }
    }
}

/* ------------------ GATv2 aggregation helpers ---------------------------- */
__device__ __forceinline__ float lrelu(float x) { return x > 0.f ? x : NEG * x; }

struct OSM { float m, s; float4 acc; };
__device__ __forceinline__ void osm_init(OSM& o) {
    o.m = -1e30f; o.s = 0.f; o.acc = make_float4(0.f, 0.f, 0.f, 0.f);
}
__device__ __forceinline__ void osm_step(OSM& o, float4 l4, float4 r4, float4 a4) {
    float p = lrelu(l4.x + r4.x) * a4.x;
    p      += lrelu(l4.y + r4.y) * a4.y;
    p      += lrelu(l4.z + r4.z) * a4.z;
    p      += lrelu(l4.w + r4.w) * a4.w;
#pragma unroll
    for (int off = 16; off > 0; off >>= 1) p += __shfl_xor_sync(0xffffffffu, p, off);
    float mn = fmaxf(o.m, p);
    float cc = __expf(o.m - mn);
    float wg = __expf(p - mn);
    o.s = o.s * cc + wg;
    o.acc.x = o.acc.x * cc + wg * l4.x;
    o.acc.y = o.acc.y * cc + wg * l4.y;
    o.acc.z = o.acc.z * cc + wg * l4.z;
    o.acc.w = o.acc.w * cc + wg * l4.w;
    o.m = mn;
}
__device__ __forceinline__ void osm_merge(OSM& a, const OSM& b) {
    float mn = fmaxf(a.m, b.m);
    float ca = __expf(a.m - mn), cb = __expf(b.m - mn);
    a.s = a.s * ca + b.s * cb;
    a.acc.x = a.acc.x * ca + b.acc.x * cb;
    a.acc.y = a.acc.y * ca + b.acc.y * cb;
    a.acc.z = a.acc.z * ca + b.acc.z * cb;
    a.acc.w = a.acc.w * ca + b.acc.w * cb;
    a.m = mn;
}

/* ------------------ layer-1 aggregation (fp16 xl, ILP-2) ----------------- */
__global__ void gat_agg1(const __half* __restrict__ xl, const float* __restrict__ xr,
                         const float* __restrict__ att, const float* __restrict__ bias,
                         __half* __restrict__ out)
{
    const int HEADS = 4, D = 512;
    int w = (blockIdx.x * blockDim.x + threadIdx.x) >> 5;
    int lane = threadIdx.x & 31;
    if (w >= N_NODES * HEADS) return;
    int dst = w / HEADS;
    int h   = w - dst * HEADS;
    int cb = h * HID + lane * 4;

    float4 a4 = *(const float4*)(att + h * HID + lane * 4);
    float4 r4 = *(const float4*)(xr + (size_t)dst * D + cb);

    OSM o0, o1;
    osm_init(o0); osm_init(o1);

    int j = g_off[dst], end = g_off[dst + 1];
    if ((end - j) & 1) {
        float4 l4 = ldh4(xl + (size_t)g_srcs[j] * D + cb);
        osm_step(o0, l4, r4, a4);
        j++;
    }
    for (; j < end; j += 2) {
        int sA = g_srcs[j], sB = g_srcs[j + 1];
        float4 lA = ldh4(xl + (size_t)sA * D + cb);
        float4 lB = ldh4(xl + (size_t)sB * D + cb);
        osm_step(o0, lA, r4, a4);
        osm_step(o1, lB, r4, a4);
    }
    osm_merge(o0, o1);

    float inv = 1.f / (o0.s + 1e-16f);
    float4 bb = *(const float4*)(bias + h * HID + lane * 4);
    float4 o4;
    o4.x = fmaxf(o0.acc.x * inv + bb.x, 0.f);
    o4.y = fmaxf(o0.acc.y * inv + bb.y, 0.f);
    o4.z = fmaxf(o0.acc.z * inv + bb.z, 0.f);
    o4.w = fmaxf(o0.acc.w * inv + bb.w, 0.f);
    st_h4(out + (size_t)dst * 512 + cb, o4);
}

/* -------- layer-2 aggregation (fp16 xl) fused with output projection ---- */
__global__ void gat_out(const __half* __restrict__ xl, const float* __restrict__ xr,
                        const float* __restrict__ att, const float* __restrict__ bias,
                        const float* __restrict__ W, const float* __restrict__ ob,
                        float* __restrict__ y)
{
    const int D = 128;
    __shared__ float Ws[HID * 10];
    __shared__ float bs[10];
    for (int i = threadIdx.x; i < HID * 10; i += blockDim.x) Ws[i] = W[i];
    if (threadIdx.x < 10) bs[threadIdx.x] = ob[threadIdx.x];
    __syncthreads();

    int w = (blockIdx.x * blockDim.x + threadIdx.x) >> 5;
    int lane = threadIdx.x & 31;
    if (w >= N_NODES) return;
    int dst = w;
    int cb = lane * 4;

    float4 a4 = *(const float4*)(att + cb);
    float4 r4 = *(const float4*)(xr + (size_t)dst * D + cb);

    OSM o0, o1;
    osm_init(o0); osm_init(o1);

    int j = g_off[dst], end = g_off[dst + 1];
    if ((end - j) & 1) {
        float4 l4 = ldh4(xl + (size_t)g_srcs[j] * D + cb);
        osm_step(o0, l4, r4, a4);
        j++;
    }
    for (; j < end; j += 2) {
        int sA = g_srcs[j], sB = g_srcs[j + 1];
        float4 lA = ldh4(xl + (size_t)sA * D + cb);
        float4 lB = ldh4(xl + (size_t)sB * D + cb);
        osm_step(o0, lA, r4, a4);
        osm_step(o1, lB, r4, a4);
    }
    osm_merge(o0, o1);

    float inv = 1.f / (o0.s + 1e-16f);
    float4 bb = *(const float4*)(bias + cb);
    float4 o4;
    o4.x = o0.acc.x * inv + bb.x;
    o4.y = o0.acc.y * inv + bb.y;
    o4.z = o0.acc.z * inv + bb.z;
    o4.w = o0.acc.w * inv + bb.w;

    int k = lane * 4;
    float p[10];
#pragma unroll
    for (int o = 0; o < 10; o++)
        p[o] = o4.x * Ws[(k + 0) * 10 + o] + o4.y * Ws[(k + 1) * 10 + o] +
               o4.z * Ws[(k + 2) * 10 + o] + o4.w * Ws[(k + 3) * 10 + o];
#pragma unroll
    for (int o = 0; o < 10; o++)
#pragma unroll
        for (int off = 16; off > 0; off >>= 1)
            p[o] += __shfl_xor_sync(0xffffffffu, p[o], off);
    if (lane < 10) y[(size_t)dst * 10 + lane] = p[lane] + bs[lane];
}

/* ------------------ launch ---------------------------------------------- */
extern "C" void kernel_launch(void* const* d_in, const int* in_sizes, int n_in,
                              void* d_out, int out_size)
{
    const float* x_player   = (const float*)d_in[0];
    const int*   edge_index = (const int*)  d_in[1];
    const float* emb        = (const float*)d_in[2];
    const float* proj_W     = (const float*)d_in[3];
    const float* proj_b     = (const float*)d_in[4];
    const float* W1l        = (const float*)d_in[5];
    const float* W1r        = (const float*)d_in[6];
    const float* att1       = (const float*)d_in[7];
    const float* b1         = (const float*)d_in[8];
    const float* W2l        = (const float*)d_in[9];
    const float* W2r        = (const float*)d_in[10];
    const float* att2       = (const float*)d_in[11];
    const float* b2         = (const float*)d_in[12];
    const float* out_W      = (const float*)d_in[13];
    const float* out_b      = (const float*)d_in[14];
    float* y = (float*)d_out;

    __half *xin, *x0, *x1, *pW, *W1, *W2, *xl1h, *xl2h;
    float *xr1f, *xr2f;
    cudaGetSymbolAddress((void**)&xin,  g_xin);
    cudaGetSymbolAddress((void**)&x0,   g_x0);
    cudaGetSymbolAddress((void**)&x1,   g_x1);
    cudaGetSymbolAddress((void**)&xl1h, g_xl1h); cudaGetSymbolAddress((void**)&xr1f, g_xr1f);
    cudaGetSymbolAddress((void**)&xl2h, g_xl2h); cudaGetSymbolAddress((void**)&xr2f, g_xr2f);
    cudaGetSymbolAddress((void**)&pW,   g_pW);
    cudaGetSymbolAddress((void**)&W1,   g_W1);
    cudaGetSymbolAddress((void**)&W2,   g_W2);

    cudaFuncSetAttribute(mm_fp16, cudaFuncAttributeMaxDynamicSharedMemorySize, SM_SZ);

    /* prep (edge count + gather + weight conversion), then CSR scan+scatter */
    k_prep<<<(PREP_TOT + 255) / 256, 256>>>(edge_index, x_player, emb, proj_W,
                                            W1l, W1r, W2l, W2r);
    k_scan   <<<1, 1024>>>();
    k_scatter<<<(N_EDGES + 255) / 256, 256>>>(edge_index);

    /* proj: [MPAD,192]@[192,128] + b, relu -> fp16 x0 */
    mm_fp16<<<dim3(1, MPAD / 64), 256, SM_SZ>>>(
        xin, pW, proj_b, x0, nullptr, nullptr, KIN, 0, HID, 1);

    /* GAT layer 1 linear: merged GEMM N=1024 -> xl fp16 | xr fp32 */
    mm_fp16<<<dim3(8, MPAD / 64), 256, SM_SZ>>>(
        x0, W1, nullptr, nullptr, xl1h, xr1f, HID, 512, 1024, 0);
    gat_agg1<<<(N_NODES * 4 * 32 + 255) / 256, 256>>>(xl1h, xr1f, att1, b1, x1);

    /* GAT layer 2 linear: merged GEMM N=256 -> xl fp16 | xr fp32 */
    mm_fp16<<<dim3(2, MPAD / 64), 256, SM_SZ>>>(
        x1, W2, nullptr, nullptr, xl2h, xr2f, 512, 128, 256, 0);

    /* layer-2 aggregation fused with output projection */
    gat_out<<<(N_NODES * 32 + 255) / 256, 256>>>(xl2h, xr2f, att2, b2, out_W, out_b, y);
}